// round 3
// baseline (speedup 1.0000x reference)
#include <cuda_runtime.h>
#include <cuda_bf16.h>
#include <stdint.h>

// Problem constants (fixed by the dataset)
#define N_STAGES 100
#define N_TREES  3
#define M_TOT    (N_STAGES * N_TREES)   // 300 trees
#define TREE_DEPTH 6
#define N_INT    63                     // internal nodes per tree
#define N_LEAF   64                     // leaves per tree (pad node table to 64)
#define NF       32                     // features
#define LR       0.1f

#define BLOCK     352                   // 11 warps; 143 blocks -> one wave on 148 SMs
#define XS_STRIDE 33                    // pad x rows to reduce bank conflicts

// SMEM: node table (uint2 {feat, thr_bits}) padded to 64/tree + x staging
#define NODES_BYTES (M_TOT * N_LEAF * (int)sizeof(uint2))      // 153600
#define XS_BYTES    (BLOCK * XS_STRIDE * (int)sizeof(float))   // 46464
#define SMEM_BYTES  (NODES_BYTES + XS_BYTES)                   // 200064 < 227KB

__global__ __launch_bounds__(BLOCK, 1)
void gbt_kernel(const float* __restrict__ x,
                const int*   __restrict__ feat,
                const float* __restrict__ thr,
                const float* __restrict__ lv,
                const float* __restrict__ init_pred,
                float* __restrict__ out,
                int N)
{
    extern __shared__ unsigned char smem_raw[];
    uint2* nodes = reinterpret_cast<uint2*>(smem_raw);                  // [300*64]
    float* xs    = reinterpret_cast<float*>(smem_raw + NODES_BYTES);    // [BLOCK*33]

    const int tid = threadIdx.x;

    // ---- Stage node table into SMEM (pad each tree to 64 entries) ----
    #pragma unroll 4
    for (int k = tid; k < M_TOT * N_LEAF; k += BLOCK) {
        int m = k >> 6;        // tree id
        int i = k & 63;        // node id within tree
        uint2 v;
        if (i < N_INT) {
            v.x = (unsigned)__ldg(feat + m * N_INT + i);
            v.y = __float_as_uint(__ldg(thr + m * N_INT + i));
        } else {
            v.x = 0u; v.y = 0u;
        }
        nodes[k] = v;
    }

    // ---- Stage this block's x rows into SMEM (coalesced LDG) ----
    const int rowBase = blockIdx.x * BLOCK;
    #pragma unroll 4
    for (int k = tid; k < BLOCK * NF; k += BLOCK) {
        int r = k >> 5;        // row within block
        int f = k & 31;        // feature
        int row = rowBase + r;
        xs[r * XS_STRIDE + f] = (row < N) ? __ldg(x + row * NF + f) : 0.0f;
    }
    __syncthreads();

    const int row = rowBase + tid;
    if (row >= N) return;

    const float* __restrict__ xr = xs + tid * XS_STRIDE;

    float acc0 = 0.0f, acc1 = 0.0f, acc2 = 0.0f;
    const uint2* __restrict__ np = nodes;     // advances 192 entries per stage
    const float* __restrict__ lvs = lv;       // advances 192 floats per stage

    for (int s = 0; s < N_STAGES; ++s) {
        int i0 = 0, i1 = 0, i2 = 0;           // 3 independent traversal chains (ILP)
        #pragma unroll
        for (int d = 0; d < TREE_DEPTH; ++d) {
            uint2 n0 = np[i0];
            uint2 n1 = np[64  + i1];
            uint2 n2 = np[128 + i2];
            float x0 = xr[n0.x];
            float x1 = xr[n1.x];
            float x2 = xr[n2.x];
            // sklearn convention: left (2i+1) iff x <= thr, else right (2i+2)
            i0 = 2 * i0 + 1 + (x0 > __uint_as_float(n0.y) ? 1 : 0);
            i1 = 2 * i1 + 1 + (x1 > __uint_as_float(n1.y) ? 1 : 0);
            i2 = 2 * i2 + 1 + (x2 > __uint_as_float(n2.y) ? 1 : 0);
        }
        // leaf index = idx - 63; leaves are L2/L1 resident (76.8 KB total)
        acc0 += __ldg(lvs +            (i0 - N_INT));
        acc1 += __ldg(lvs + N_LEAF   + (i1 - N_INT));
        acc2 += __ldg(lvs + 2*N_LEAF + (i2 - N_INT));
        np  += N_TREES * N_LEAF;   // 192 nodes per stage
        lvs += N_TREES * N_LEAF;   // 192 leaves per stage
    }

    out[row * N_TREES + 0] = __ldg(init_pred + 0) + LR * acc0;
    out[row * N_TREES + 1] = __ldg(init_pred + 1) + LR * acc1;
    out[row * N_TREES + 2] = __ldg(init_pred + 2) + LR * acc2;
}

extern "C" void kernel_launch(void* const* d_in, const int* in_sizes, int n_in,
                              void* d_out, int out_size)
{
    const float* x    = (const float*)d_in[0];   // [N, 32] f32
    const int*   feat = (const int*)  d_in[1];   // [100, 3, 63] i32
    const float* thr  = (const float*)d_in[2];   // [100, 3, 63] f32
    const float* lv   = (const float*)d_in[3];   // [100, 3, 64] f32
    const float* ip   = (const float*)d_in[4];   // [3] f32
    float* out = (float*)d_out;                  // [N, 3] f32

    const int N = in_sizes[0] / NF;

    // Opt-in to >48KB dynamic smem (not a stream op; safe under graph capture).
    cudaFuncSetAttribute(gbt_kernel,
                         cudaFuncAttributeMaxDynamicSharedMemorySize, SMEM_BYTES);

    const int grid = (N + BLOCK - 1) / BLOCK;    // 143 blocks for N=50000
    gbt_kernel<<<grid, BLOCK, SMEM_BYTES>>>(x, feat, thr, lv, ip, out, N);
}

// round 4
// speedup vs baseline: 1.0057x; 1.0057x over previous
#include <cuda_runtime.h>
#include <cuda_bf16.h>
#include <stdint.h>

// Problem constants (fixed by the dataset)
#define N_STAGES 100
#define N_TREES  3
#define M_TOT    (N_STAGES * N_TREES)   // 300 trees
#define TREE_DEPTH 6
#define N_INT    63                     // internal nodes per tree
#define N_LEAF   64                     // leaves per tree (tables padded to 64)
#define NF       32                     // features
#define LR       0.1f

#define BLOCK    352                    // 11 warps; 143 blocks -> one wave on 148 SMs

// ---- SMEM layout (all gathers provably bank-conflict-free, see theory) ----
// thr_s : [300*64] f32   (level-d indices are consecutive, span<=32 -> distinct banks)
// lv_s  : [300*64] f32   (random 32-of-64 gather, ~2-way worst case)
// xs    : [32*352] f32 transposed (bank = tid%32 for ANY feature index)
// feat_s: [300*64] u8    (16 words/tree, <=1 word per bank -> broadcast only)
#define THR_FLOATS  (M_TOT * N_LEAF)                 // 19200
#define LV_FLOATS   (M_TOT * N_LEAF)                 // 19200
#define XS_FLOATS   (NF * BLOCK)                     // 11264
#define FEAT_BYTES  (M_TOT * N_LEAF)                 // 19200
#define SMEM_BYTES  ((THR_FLOATS + LV_FLOATS + XS_FLOATS) * 4 + FEAT_BYTES)  // 217856

__global__ __launch_bounds__(BLOCK, 1)
void gbt_kernel(const float* __restrict__ x,
                const int*   __restrict__ feat,
                const float* __restrict__ thr,
                const float* __restrict__ lv,
                const float* __restrict__ init_pred,
                float* __restrict__ out,
                int N)
{
    extern __shared__ unsigned char smem_raw[];
    float*         thr_s  = reinterpret_cast<float*>(smem_raw);
    float*         lv_s   = thr_s + THR_FLOATS;
    float*         xs     = lv_s + LV_FLOATS;
    unsigned char* feat_s = reinterpret_cast<unsigned char*>(xs + XS_FLOATS);

    const int tid = threadIdx.x;
    const int rowBase = blockIdx.x * BLOCK;

    // ---- Stage node thresholds + leaves + features (pad each tree to 64) ----
    // Consecutive lanes -> consecutive smem addrs: conflict-free STS.
    #pragma unroll 4
    for (int k = tid; k < M_TOT * N_LEAF; k += BLOCK) {
        int m = k >> 6;        // tree id
        int i = k & 63;        // slot within tree
        thr_s[k]  = (i < N_INT) ? __ldg(thr  + m * N_INT + i) : 0.0f;
        lv_s[k]   = __ldg(lv + k);                       // leaves: exactly 64/tree
        feat_s[k] = (i < N_INT) ? (unsigned char)__ldg(feat + m * N_INT + i) : 0;
    }

    // ---- Stage x TRANSPOSED: xs[f*BLOCK + r] = x[rowBase+r][f] ----
    // k = f*BLOCK + r: consecutive lanes -> consecutive r (conflict-free STS);
    // each thread keeps r fixed and walks f, so its 128B x-row stays L1-hot.
    #pragma unroll 4
    for (int k = tid; k < NF * BLOCK; k += BLOCK) {
        int f = k / BLOCK;
        int r = k - f * BLOCK;
        int row = rowBase + r;
        xs[k] = (row < N) ? __ldg(x + row * NF + f) : 0.0f;
    }
    __syncthreads();

    const int row = rowBase + tid;
    if (row >= N) return;

    const float* __restrict__ xr = xs + tid;   // index with f*BLOCK: bank == lane

    float acc0 = 0.0f, acc1 = 0.0f, acc2 = 0.0f;

    const float*         thrp  = thr_s;
    const float*         lvp   = lv_s;
    const unsigned char* featp = feat_s;

    for (int s = 0; s < N_STAGES; ++s) {
        int i0 = 0, i1 = 0, i2 = 0;            // 3 independent chains (ILP)
        #pragma unroll
        for (int d = 0; d < TREE_DEPTH; ++d) {
            int f0 = featp[i0];
            int f1 = featp[64  + i1];
            int f2 = featp[128 + i2];
            float t0 = thrp[i0];
            float t1 = thrp[64  + i1];
            float t2 = thrp[128 + i2];
            float x0 = xr[f0 * BLOCK];
            float x1 = xr[f1 * BLOCK];
            float x2 = xr[f2 * BLOCK];
            // left (2i+1) iff x <= t, else right (2i+2)
            i0 = 2 * i0 + 1 + (x0 > t0 ? 1 : 0);
            i1 = 2 * i1 + 1 + (x1 > t1 ? 1 : 0);
            i2 = 2 * i2 + 1 + (x2 > t2 ? 1 : 0);
        }
        acc0 += lvp[           (i0 - N_INT)];
        acc1 += lvp[N_LEAF   + (i1 - N_INT)];
        acc2 += lvp[2*N_LEAF + (i2 - N_INT)];
        thrp  += N_TREES * N_LEAF;   // 192 per stage
        lvp   += N_TREES * N_LEAF;
        featp += N_TREES * N_LEAF;
    }

    out[row * N_TREES + 0] = __ldg(init_pred + 0) + LR * acc0;
    out[row * N_TREES + 1] = __ldg(init_pred + 1) + LR * acc1;
    out[row * N_TREES + 2] = __ldg(init_pred + 2) + LR * acc2;
}

extern "C" void kernel_launch(void* const* d_in, const int* in_sizes, int n_in,
                              void* d_out, int out_size)
{
    const float* x    = (const float*)d_in[0];   // [N, 32] f32
    const int*   feat = (const int*)  d_in[1];   // [100, 3, 63] i32
    const float* thr  = (const float*)d_in[2];   // [100, 3, 63] f32
    const float* lv   = (const float*)d_in[3];   // [100, 3, 64] f32
    const float* ip   = (const float*)d_in[4];   // [3] f32
    float* out = (float*)d_out;                  // [N, 3] f32

    const int N = in_sizes[0] / NF;

    cudaFuncSetAttribute(gbt_kernel,
                         cudaFuncAttributeMaxDynamicSharedMemorySize, SMEM_BYTES);

    const int grid = (N + BLOCK - 1) / BLOCK;    // 143 blocks for N=50000
    gbt_kernel<<<grid, BLOCK, SMEM_BYTES>>>(x, feat, thr, lv, ip, out, N);
}

// round 5
// speedup vs baseline: 1.1115x; 1.1052x over previous
#include <cuda_runtime.h>
#include <cuda_bf16.h>
#include <stdint.h>

// Problem constants (fixed by the dataset)
#define N_STAGES 100
#define N_TREES  3
#define M_TOT    (N_STAGES * N_TREES)   // 300 trees
#define TREE_DEPTH 6
#define N_INT    63
#define N_LEAF   64                     // tables padded to 64 slots/tree
#define NF       32
#define LR       0.1f

#define ROWS_PB   352                   // rows per block (11 warps' worth)
#define BLOCK     704                   // 22 warps: 2 stage-groups x 352 rows
#define HALF_ST   (N_STAGES / 2)        // 50 stages per group
#define SLOTS     (M_TOT * N_LEAF)      // 19200 node slots

// ---- SMEM layout (single 202,880B arena; all gathers conflict-free) ----
// [0      , 76800 )  thr bits   u32[19200]  (depth window <=32 consec slots)
// [76800  , 153600)  feat offs  u32[19200]  = f*ROWS_PB*4 (pre-scaled bytes)
// [153600 , 198656)  xs f32[32*352] transposed (bank = rowLocal mod 32)
// [198656 , 202880)  red f32[352*3] cross-group partial sums
#define OFF_THR  0
#define OFF_FO   (SLOTS * 4)            // 76800
#define OFF_XS   (2 * SLOTS * 4)        // 153600
#define OFF_RED  (OFF_XS + NF * ROWS_PB * 4)  // 198656
#define SMEM_BYTES (OFF_RED + ROWS_PB * N_TREES * 4)  // 202880

__global__ __launch_bounds__(BLOCK, 1)
void gbt_kernel(const float* __restrict__ x,
                const int*   __restrict__ feat,
                const float* __restrict__ thr,
                const float* __restrict__ lv,
                const float* __restrict__ init_pred,
                float* __restrict__ out,
                int N)
{
    extern __shared__ unsigned char sm[];
    uint32_t* thr_s = reinterpret_cast<uint32_t*>(sm + OFF_THR);
    uint32_t* fo_s  = reinterpret_cast<uint32_t*>(sm + OFF_FO);
    float*    xs    = reinterpret_cast<float*>(sm + OFF_XS);
    float*    red   = reinterpret_cast<float*>(sm + OFF_RED);

    const int tid = threadIdx.x;
    const int rowBase = blockIdx.x * ROWS_PB;

    // ---- Stage node tables (pad each tree to 64 slots) ----
    #pragma unroll 4
    for (int k = tid; k < SLOTS; k += BLOCK) {
        int m = k >> 6, i = k & 63;
        uint32_t tb = 0, fo = 0;
        if (i < N_INT) {
            tb = __float_as_uint(__ldg(thr + m * N_INT + i));
            fo = (uint32_t)__ldg(feat + m * N_INT + i) * (ROWS_PB * 4);
        }
        thr_s[k] = tb;
        fo_s[k]  = fo;
    }

    // ---- Stage x transposed: xs[f*ROWS_PB + r] ----
    #pragma unroll 4
    for (int k = tid; k < NF * ROWS_PB; k += BLOCK) {
        int f = k / ROWS_PB;
        int r = k - f * ROWS_PB;
        int row = rowBase + r;
        xs[k] = (row < N) ? __ldg(x + row * NF + f) : 0.0f;
    }
    __syncthreads();

    const int grp = tid / ROWS_PB;          // 0: stages 0-49, 1: stages 50-99
    const int rl  = tid - grp * ROWS_PB;    // row within block
    const int row = rowBase + rl;

    float acc0 = 0.0f, acc1 = 0.0f, acc2 = 0.0f;

    if (row < N) {
        const char* xb = reinterpret_cast<const char*>(xs) + rl * 4;
        int base = grp * HALF_ST * (N_TREES * N_LEAF);   // absolute node slot

        #pragma unroll 1
        for (int s = 0; s < HALF_ST; ++s) {
            int a0 = base, a1 = base + 64, a2 = base + 128;
            const int K0 = 1 - a0, K1 = 1 - a1, K2 = 1 - a2;  // a' = 2a+K+p
            #pragma unroll
            for (int d = 0; d < TREE_DEPTH; ++d) {
                uint32_t t0 = thr_s[a0], t1 = thr_s[a1], t2 = thr_s[a2];
                uint32_t f0 = fo_s[a0],  f1 = fo_s[a1],  f2 = fo_s[a2];
                float x0 = *reinterpret_cast<const float*>(xb + f0);
                float x1 = *reinterpret_cast<const float*>(xb + f1);
                float x2 = *reinterpret_cast<const float*>(xb + f2);
                a0 = a0 + a0 + K0 + ((x0 > __uint_as_float(t0)) ? 1 : 0);
                a1 = a1 + a1 + K1 + ((x1 > __uint_as_float(t1)) ? 1 : 0);
                a2 = a2 + a2 + K2 + ((x2 > __uint_as_float(t2)) ? 1 : 0);
            }
            // leaf slot = a - 63 in the [300*64] leaf layout (identity mapping)
            acc0 += __ldg(lv + (a0 - N_INT));
            acc1 += __ldg(lv + (a1 - N_INT));
            acc2 += __ldg(lv + (a2 - N_INT));
            base += N_TREES * N_LEAF;   // 192 slots per stage
        }
    }

    // ---- Cross-group reduction ----
    if (grp == 1 && row < N) {
        red[rl * 3 + 0] = acc0;
        red[rl * 3 + 1] = acc1;
        red[rl * 3 + 2] = acc2;
    }
    __syncthreads();
    if (grp == 0 && row < N) {
        out[row * 3 + 0] = __ldg(init_pred + 0) + LR * (acc0 + red[rl * 3 + 0]);
        out[row * 3 + 1] = __ldg(init_pred + 1) + LR * (acc1 + red[rl * 3 + 1]);
        out[row * 3 + 2] = __ldg(init_pred + 2) + LR * (acc2 + red[rl * 3 + 2]);
    }
}

extern "C" void kernel_launch(void* const* d_in, const int* in_sizes, int n_in,
                              void* d_out, int out_size)
{
    const float* x    = (const float*)d_in[0];   // [N, 32] f32
    const int*   feat = (const int*)  d_in[1];   // [100, 3, 63] i32
    const float* thr  = (const float*)d_in[2];   // [100, 3, 63] f32
    const float* lv   = (const float*)d_in[3];   // [100, 3, 64] f32
    const float* ip   = (const float*)d_in[4];   // [3] f32
    float* out = (float*)d_out;                  // [N, 3] f32

    const int N = in_sizes[0] / NF;

    cudaFuncSetAttribute(gbt_kernel,
                         cudaFuncAttributeMaxDynamicSharedMemorySize, SMEM_BYTES);

    const int grid = (N + ROWS_PB - 1) / ROWS_PB;  // 143 blocks -> one wave
    gbt_kernel<<<grid, BLOCK, SMEM_BYTES>>>(x, feat, thr, lv, ip, out, N);
}